// round 13
// baseline (speedup 1.0000x reference)
#include <cuda_runtime.h>
#include <cuda_bf16.h>
#include <cstdint>

// ---------------------------------------------------------------------------
// QTT-3D sampling, single persistent kernel with device-wide barriers.
// core0 (1,8,8) core1 (8,8,64) core2 (64,8,256) core3 (256,8,256)
// core4 (256,8,256) core5 (256,8,64) core6 (64,8,8) core7 (8,8,1)
// prefix P = p012*8+g3   -> M0123[P][256]
// suffix S = g4*512+s567 -> W4567[S][256]
// out[n] = dot(M0123[P(n)], W4567[S(n)])
// Phase 1 (CTAs 0..63): build bf16 hi/lo A tables (smem tile GEMM).
// Phase 2 (all 128):     16x 512x256x256 GEMM on mma.sync bf16, 3-term
//                        hi/lo split, double-buffered smem pipeline.
// Phase 3 (all 128):     sampling, 4 samples per warp.
// 128 CTAs <= 148 SMs -> all co-resident -> atomic grid barrier is safe.
// ---------------------------------------------------------------------------

#define NBLK 128

__device__ __align__(128) float g_M0123[4096 * 256];
__device__ __align__(128) float g_W4567[4096 * 256];
__device__ __align__(128) __nv_bfloat16 g_Ap_hi[512 * 256];  // M012
__device__ __align__(128) __nv_bfloat16 g_Ap_lo[512 * 256];
__device__ __align__(128) __nv_bfloat16 g_As_hi[512 * 256];  // W567
__device__ __align__(128) __nv_bfloat16 g_As_lo[512 * 256];
__device__ unsigned g_bar = 0;   // monotonic; replay-safe

__device__ __forceinline__ void grid_sync() {
    __threadfence();
    __syncthreads();
    if (threadIdx.x == 0) {
        unsigned my = atomicAdd(&g_bar, 1u);
        unsigned target = my - (my % NBLK) + NBLK;
        unsigned v;
        do {
            asm volatile("ld.volatile.global.u32 %0, [%1];" : "=r"(v) : "l"(&g_bar));
        } while ((int)(v - target) < 0);
    }
    __syncthreads();
    __threadfence();
}

__device__ __forceinline__ void bsplit(float v, __nv_bfloat16& h, __nv_bfloat16& l) {
    h = __float2bfloat16(v);
    l = __float2bfloat16(v - __bfloat162float(h));
}

__device__ __forceinline__ void mma16816(float* d, const uint32_t* a, const uint32_t* b) {
    asm volatile(
        "mma.sync.aligned.m16n8k16.row.col.f32.bf16.bf16.f32 "
        "{%0,%1,%2,%3}, {%4,%5,%6,%7}, {%8,%9}, {%0,%1,%2,%3};"
        : "+f"(d[0]), "+f"(d[1]), "+f"(d[2]), "+f"(d[3])
        : "r"(a[0]), "r"(a[1]), "r"(a[2]), "r"(a[3]), "r"(b[0]), "r"(b[1]));
}

__device__ __forceinline__ void ldsm_x4(uint32_t* r, const void* p) {
    uint32_t a = (uint32_t)__cvta_generic_to_shared(p);
    asm volatile("ldmatrix.sync.aligned.m8n8.x4.shared.b16 {%0,%1,%2,%3}, [%4];"
        : "=r"(r[0]), "=r"(r[1]), "=r"(r[2]), "=r"(r[3]) : "r"(a));
}
__device__ __forceinline__ void ldsm_x4t(uint32_t* r, const void* p) {
    uint32_t a = (uint32_t)__cvta_generic_to_shared(p);
    asm volatile("ldmatrix.sync.aligned.m8n8.x4.trans.shared.b16 {%0,%1,%2,%3}, [%4];"
        : "=r"(r[0]), "=r"(r[1]), "=r"(r[2]), "=r"(r[3]) : "r"(a));
}

#define KST 40      // A / suffix-B smem row stride (halves)
#define PBST 136    // prefix-B smem row stride (halves)
#define BUFH 20480  // halves per pipeline stage (4 x 5120)
#define SMEM_BYTES (2 * BUFH * 2)   // 81920

extern "C" __global__ void __launch_bounds__(256)
qtt_fused(const float* __restrict__ c0, const float* __restrict__ c1,
          const float* __restrict__ c2, const float* __restrict__ c3,
          const float* __restrict__ c4, const float* __restrict__ c5,
          const float* __restrict__ c6, const float* __restrict__ c7,
          const int* __restrict__ coords, float* __restrict__ out)
{
    extern __shared__ __align__(16) char dynsmem[];
    const int tid = threadIdx.x;
    const int bx = blockIdx.x;

    // ======================= Phase 1: A tables =======================
    if (bx < 64) {
        float* sSrc = (float*)dynsmem;             // 64*72*4 = 18432 B
        float* sFac = (float*)(dynsmem + 18432);   // 18432 B

        const bool pref = bx < 32;
        const int gg = (bx >> 2) & 7;
        const int t0 = (bx & 3) * 64;

        if (pref) {
#pragma unroll
            for (int i = 0; i < 4; i++) {
                int u = i * 256 + tid;
                int r = u >> 4;
                int cc = (u & 15) * 4;
                float4 v = *(const float4*)(c2 + (r * 8 + gg) * 256 + t0 + cc);
                *(float4*)(sSrc + r * 72 + cc) = v;
            }
            {
                int p = tid >> 2, g0 = p >> 3, g1 = p & 7;
                int rq = (tid & 3) * 16;
                float a[8];
#pragma unroll
                for (int j = 0; j < 8; j++) a[j] = c0[g0 * 8 + j];
#pragma unroll
                for (int rr = 0; rr < 16; rr++) {
                    int r = rq + rr;
                    float acc = 0.f;
#pragma unroll
                    for (int j = 0; j < 8; j++)
                        acc += a[j] * c1[(j * 8 + g1) * 64 + r];
                    sFac[r * 72 + p] = acc;
                }
            }
        } else {
#pragma unroll
            for (int i = 0; i < 4; i++) {
                int u = i * 256 + tid;
                int t = u >> 4;
                int cc = (u & 15) * 4;
                float4 v = *(const float4*)(c5 + ((t0 + t) * 8 + gg) * 64 + cc);
                float* d = sSrc + t * 65 + cc;
                d[0] = v.x; d[1] = v.y; d[2] = v.z; d[3] = v.w;
            }
            {
                int q = tid >> 2, g6 = q >> 3, g7 = q & 7;
                int rq = (tid & 3) * 16;
                float b7[8];
#pragma unroll
                for (int j = 0; j < 8; j++) b7[j] = c7[j * 8 + g7];
#pragma unroll
                for (int rr = 0; rr < 16; rr++) {
                    int r = rq + rr;
                    float acc = 0.f;
#pragma unroll
                    for (int j = 0; j < 8; j++)
                        acc += c6[(r * 8 + g6) * 8 + j] * b7[j];
                    sFac[r * 72 + q] = acc;
                }
            }
        }
        __syncthreads();

        const int p4 = tid >> 4;
        const int t4 = tid & 15;
        float acc[4][4];
#pragma unroll
        for (int i = 0; i < 4; i++)
#pragma unroll
            for (int j = 0; j < 4; j++) acc[i][j] = 0.f;

        if (pref) {
#pragma unroll 8
            for (int r = 0; r < 64; r++) {
                float4 a = *(const float4*)(sFac + r * 72 + p4 * 4);
                float4 b = *(const float4*)(sSrc + r * 72 + t4 * 4);
                float av[4] = {a.x, a.y, a.z, a.w};
                float bv[4] = {b.x, b.y, b.z, b.w};
#pragma unroll
                for (int i = 0; i < 4; i++)
#pragma unroll
                    for (int j = 0; j < 4; j++)
                        acc[i][j] = fmaf(av[i], bv[j], acc[i][j]);
            }
        } else {
#pragma unroll 8
            for (int r = 0; r < 64; r++) {
                float4 a = *(const float4*)(sFac + r * 72 + p4 * 4);
                float av[4] = {a.x, a.y, a.z, a.w};
                float bv[4];
#pragma unroll
                for (int j = 0; j < 4; j++)
                    bv[j] = sSrc[(t4 * 4 + j) * 65 + r];
#pragma unroll
                for (int i = 0; i < 4; i++)
#pragma unroll
                    for (int j = 0; j < 4; j++)
                        acc[i][j] = fmaf(av[i], bv[j], acc[i][j]);
            }
        }

        __nv_bfloat16* __restrict__ H = pref ? g_Ap_hi : g_As_hi;
        __nv_bfloat16* __restrict__ L = pref ? g_Ap_lo : g_As_lo;
#pragma unroll
        for (int i = 0; i < 4; i++) {
            int prow = p4 * 4 + i;
            int orow = pref ? (prow * 8 + gg) : (gg * 64 + prow);
            __nv_bfloat16 h[4], l[4];
#pragma unroll
            for (int j = 0; j < 4; j++) bsplit(acc[i][j], h[j], l[j]);
            *(uint2*)(H + orow * 256 + t0 + t4 * 4) = *(uint2*)h;
            *(uint2*)(L + orow * 256 + t0 + t4 * 4) = *(uint2*)l;
        }
    }

    grid_sync();

    // ======================= Phase 2: GEMM ===========================
    {
        const int mtile = bx & 3;
        const int ntile = (bx >> 2) & 1;
        const int z = bx >> 3;                 // 0..15
        const bool prefix = (z < 8);
        const int g = z & 7;
        const int m0 = mtile * 128;
        const int n0 = ntile * 128;

        const __nv_bfloat16* __restrict__ Ah = prefix ? g_Ap_hi : g_As_hi;
        const __nv_bfloat16* __restrict__ Al = prefix ? g_Ap_lo : g_As_lo;

        __nv_bfloat16* sm = (__nv_bfloat16*)dynsmem;

        const int wid = tid >> 5;
        const int lane = tid & 31;
        const int wy = wid >> 2;
        const int wx = wid & 3;
        const int i4 = lane >> 3;
        const int r8 = lane & 7;

        const int grow = tid >> 2;
        const int gkq = (tid & 3) * 8;
        const int pkq = tid >> 3;
        const int pns = (tid & 7) * 16;
        const int srow = tid >> 1;
        const int sks = (tid & 1) * 16;

        float acc[4][4][4];
#pragma unroll
        for (int mi = 0; mi < 4; mi++)
#pragma unroll
            for (int ni = 0; ni < 4; ni++)
#pragma unroll
                for (int q = 0; q < 4; q++) acc[mi][ni][q] = 0.f;

        uint4 pAh0, pAh1, pAl0, pAl1;
        float4 fB[4];

        auto LOAD = [&](int k0) {
            int oa0 = (m0 + grow) * 256 + k0 + gkq;
            int oa1 = (m0 + grow + 64) * 256 + k0 + gkq;
            pAh0 = *(const uint4*)(Ah + oa0);  pAh1 = *(const uint4*)(Ah + oa1);
            pAl0 = *(const uint4*)(Al + oa0);  pAl1 = *(const uint4*)(Al + oa1);
            if (prefix) {
                const float* src = c3 + ((k0 + pkq) * 8 + g) * 256 + n0 + pns;
#pragma unroll
                for (int j = 0; j < 4; j++) fB[j] = *(const float4*)(src + j * 4);
            } else {
                const float* src = c4 + ((n0 + srow) * 8 + g) * 256 + k0 + sks;
#pragma unroll
                for (int j = 0; j < 4; j++) fB[j] = *(const float4*)(src + j * 4);
            }
        };

        auto STS = [&](int buf) {
            __nv_bfloat16* sAh = sm + buf * BUFH;
            __nv_bfloat16* sAl = sAh + 5120;
            __nv_bfloat16* sBh = sAh + 10240;
            __nv_bfloat16* sBl = sAh + 15360;
            int d0 = grow * KST + gkq;
            int d1 = (grow + 64) * KST + gkq;
            *(uint4*)(sAh + d0) = pAh0;  *(uint4*)(sAh + d1) = pAh1;
            *(uint4*)(sAl + d0) = pAl0;  *(uint4*)(sAl + d1) = pAl1;
            __nv_bfloat16 hh[16], ll[16];
#pragma unroll
            for (int j = 0; j < 4; j++) {
                bsplit(fB[j].x, hh[j * 4 + 0], ll[j * 4 + 0]);
                bsplit(fB[j].y, hh[j * 4 + 1], ll[j * 4 + 1]);
                bsplit(fB[j].z, hh[j * 4 + 2], ll[j * 4 + 2]);
                bsplit(fB[j].w, hh[j * 4 + 3], ll[j * 4 + 3]);
            }
            int db = prefix ? (pkq * PBST + pns) : (srow * KST + sks);
            *(uint4*)(sBh + db)     = *(uint4*)(hh);
            *(uint4*)(sBh + db + 8) = *(uint4*)(hh + 8);
            *(uint4*)(sBl + db)     = *(uint4*)(ll);
            *(uint4*)(sBl + db + 8) = *(uint4*)(ll + 8);
        };

        // prologue: fill stage 0, prefetch chunk 1
        LOAD(0);
        STS(0);
        LOAD(32);
        __syncthreads();

        for (int c = 0; c < 8; c++) {
            if (c < 7) STS((c + 1) & 1);     // overlapped with compute below
            if (c < 6) LOAD((c + 2) * 32);
            // compute chunk c from stage c&1
            __nv_bfloat16* sAh = sm + (c & 1) * BUFH;
            __nv_bfloat16* sAl = sAh + 5120;
            __nv_bfloat16* sBh = sAh + 10240;
            __nv_bfloat16* sBl = sAh + 15360;
#pragma unroll
            for (int kk = 0; kk < 32; kk += 16) {
                uint32_t ah[4][4], al[4][4], bh[4][2], bl[4][2];
                int a_base = (wy * 64 + (i4 & 1) * 8 + r8) * KST + kk + (i4 >> 1) * 8;
#pragma unroll
                for (int mi = 0; mi < 4; mi++) {
                    ldsm_x4(ah[mi], sAh + a_base + mi * 16 * KST);
                    ldsm_x4(al[mi], sAl + a_base + mi * 16 * KST);
                }
                if (prefix) {
                    int b_base = (kk + (i4 & 1) * 8 + r8) * PBST + wx * 32 + (i4 >> 1) * 8;
#pragma unroll
                    for (int nip = 0; nip < 2; nip++) {
                        uint32_t r[4];
                        ldsm_x4t(r, sBh + b_base + nip * 16);
                        bh[nip * 2][0] = r[0]; bh[nip * 2][1] = r[1];
                        bh[nip * 2 + 1][0] = r[2]; bh[nip * 2 + 1][1] = r[3];
                        ldsm_x4t(r, sBl + b_base + nip * 16);
                        bl[nip * 2][0] = r[0]; bl[nip * 2][1] = r[1];
                        bl[nip * 2 + 1][0] = r[2]; bl[nip * 2 + 1][1] = r[3];
                    }
                } else {
                    int b_base = (wx * 32 + (i4 >> 1) * 8 + r8) * KST + kk + (i4 & 1) * 8;
#pragma unroll
                    for (int nip = 0; nip < 2; nip++) {
                        uint32_t r[4];
                        ldsm_x4(r, sBh + b_base + nip * 16 * KST);
                        bh[nip * 2][0] = r[0]; bh[nip * 2][1] = r[1];
                        bh[nip * 2 + 1][0] = r[2]; bh[nip * 2 + 1][1] = r[3];
                        ldsm_x4(r, sBl + b_base + nip * 16 * KST);
                        bl[nip * 2][0] = r[0]; bl[nip * 2][1] = r[1];
                        bl[nip * 2 + 1][0] = r[2]; bl[nip * 2 + 1][1] = r[3];
                    }
                }
#pragma unroll
                for (int mi = 0; mi < 4; mi++)
#pragma unroll
                    for (int ni = 0; ni < 4; ni++) {
                        mma16816(acc[mi][ni], ah[mi], bh[ni]);
                        mma16816(acc[mi][ni], ah[mi], bl[ni]);
                        mma16816(acc[mi][ni], al[mi], bh[ni]);
                    }
            }
            __syncthreads();
        }

        const int fr = lane >> 2;
        const int fc = (lane & 3) * 2;
#pragma unroll
        for (int mi = 0; mi < 4; mi++) {
#pragma unroll
            for (int ni = 0; ni < 4; ni++) {
                int m = m0 + wy * 64 + mi * 16 + fr;
                int n = n0 + wx * 32 + ni * 8 + fc;
                float* dst0;
                float* dst1;
                if (prefix) {
                    dst0 = g_M0123 + (m * 8 + g) * 256 + n;
                    dst1 = g_M0123 + ((m + 8) * 8 + g) * 256 + n;
                } else {
                    dst0 = g_W4567 + (g * 512 + m) * 256 + n;
                    dst1 = g_W4567 + (g * 512 + m + 8) * 256 + n;
                }
                *(float2*)dst0 = make_float2(acc[mi][ni][0], acc[mi][ni][1]);
                *(float2*)dst1 = make_float2(acc[mi][ni][2], acc[mi][ni][3]);
            }
        }
    }

    grid_sync();

    // ======================= Phase 3: sampling =======================
    {
        const int wid = tid >> 5;
        const int lane = tid & 31;
        const int gw = bx * 8 + wid;          // 0..1023
#pragma unroll
        for (int i = 0; i < 4; i++) {
            int s = gw * 4 + i;               // 0..4095
            int x = coords[s * 3 + 0];
            int y = coords[s * 3 + 1];
            int zc = coords[s * 3 + 2];
            int P = 0, S = 0;
#pragma unroll
            for (int l = 0; l < 8; l++) {
                int sh = 7 - l;
                int b = (((x >> sh) & 1) << 2) | (((y >> sh) & 1) << 1) | ((zc >> sh) & 1);
                if (l < 4) P = (P << 3) | b;
                else       S = (S << 3) | b;
            }
            const float4* a = (const float4*)(g_M0123 + P * 256);
            const float4* w = (const float4*)(g_W4567 + S * 256);
            float4 a0 = a[lane], a1 = a[lane + 32];
            float4 b0 = w[lane], b1 = w[lane + 32];
            float acc = a0.x * b0.x + a0.y * b0.y + a0.z * b0.z + a0.w * b0.w
                      + a1.x * b1.x + a1.y * b1.y + a1.z * b1.z + a1.w * b1.w;
#pragma unroll
            for (int o = 16; o > 0; o >>= 1)
                acc += __shfl_xor_sync(0xFFFFFFFFu, acc, o);
            if (lane == 0) out[s] = acc;
        }
    }
}

// ---------------------------------------------------------------------------
extern "C" void kernel_launch(void* const* d_in, const int* in_sizes, int n_in,
                              void* d_out, int out_size)
{
    (void)in_sizes; (void)n_in; (void)out_size;
    const float* c0 = (const float*)d_in[0];
    const float* c1 = (const float*)d_in[1];
    const float* c2 = (const float*)d_in[2];
    const float* c3 = (const float*)d_in[3];
    const float* c4 = (const float*)d_in[4];
    const float* c5 = (const float*)d_in[5];
    const float* c6 = (const float*)d_in[6];
    const float* c7 = (const float*)d_in[7];
    const int* coords = (const int*)d_in[8];
    float* out = (float*)d_out;

    cudaFuncSetAttribute(qtt_fused, cudaFuncAttributeMaxDynamicSharedMemorySize,
                         SMEM_BYTES);
    qtt_fused<<<NBLK, 256, SMEM_BYTES>>>(c0, c1, c2, c3, c4, c5, c6, c7,
                                         coords, out);
}